// round 13
// baseline (speedup 1.0000x reference)
#include <cuda_runtime.h>
#include <cuda_bf16.h>
#include <cstdint>

#define NBATCH 8192
#define SETS   4
#define GRID   (NBATCH/SETS)
#define TPB    512
#define NLAT   16

#define SA 136            // halfword stride for A1/W2/W3 [.][k] bf16 arrays
#define PLANE_A  34816    // 128*136*2 bytes
#define PLANE_W2 34816
#define PLANE_W3 8704     // 32*136*2

// ---------------- shared memory layout (bytes) ----------------
#define O_W2B 0           // W2 as B: [n=128][k=136] bf16, hi+lo planes (69632)
#define O_W3B 69632       // W3 as B: [n=32][k=136] bf16, hi+lo planes (17408)
#define O_A1  87040       // A: [m=128][k=136] bf16, hi+lo planes (69632)
#define O_WP  156672      // fspool weights f32 [32][128] (16384)
#define O_ZP0 173056      // Z accum plane f32 [32][132] (16896), set parity 0
#define O_ZP1 189952      // set parity 1 (16896)
#define O_X   206848      // 2048
#define O_W1  208896      // 2048
#define O_B1  210944      // 512
#define O_B2  211456      // 512
#define O_B3  211968      // 128
#define SMEM_BYTES 212096

__device__ __forceinline__ uint32_t cvta_smem(const void* p) {
    uint32_t a;
    asm("{ .reg .u64 t; cvta.to.shared.u64 t, %1; cvt.u32.u64 %0, t; }" : "=r"(a) : "l"(p));
    return a;
}
__device__ __forceinline__ uint32_t pack_bf16x2(float lo, float hi) {
    __nv_bfloat162 t;
    t.x = __float2bfloat16_rn(lo);
    t.y = __float2bfloat16_rn(hi);
    return *(uint32_t*)&t;
}

#define LDSM4(R0,R1,R2,R3,ADDR) \
    asm volatile("ldmatrix.sync.aligned.m8n8.x4.shared.b16 {%0,%1,%2,%3}, [%4];" \
        : "=r"(R0),"=r"(R1),"=r"(R2),"=r"(R3) : "r"(ADDR) : "memory")

#define MMA(C,A,B) \
    asm volatile("mma.sync.aligned.m16n8k16.row.col.f32.bf16.bf16.f32 " \
        "{%0,%1,%2,%3}, {%4,%5,%6,%7}, {%8,%9}, {%0,%1,%2,%3};" \
        : "+f"((C)[0]),"+f"((C)[1]),"+f"((C)[2]),"+f"((C)[3]) \
        : "r"((A)[0]),"r"((A)[1]),"r"((A)[2]),"r"((A)[3]), "r"((B)[0]),"r"((B)[1]))

__global__ __launch_bounds__(TPB, 1)
void enc_kernel(const float* __restrict__ x,  const float* __restrict__ W1,
                const float* __restrict__ b1, const float* __restrict__ W2,
                const float* __restrict__ b2, const float* __restrict__ W3,
                const float* __restrict__ b3, const float* __restrict__ pwm,
                const float* __restrict__ eps, float* __restrict__ out)
{
    extern __shared__ __align__(1024) char smem[];
    const uint32_t sb = cvta_smem(smem);
    const int tid = threadIdx.x;
    const int wid = tid >> 5, lane = tid & 31;
    const int g = lane >> 2, t4 = lane & 3;
    const int l8 = lane & 7, mi = lane >> 3;

    __nv_bfloat16* sW2B = (__nv_bfloat16*)(smem + O_W2B);
    __nv_bfloat16* sW3B = (__nv_bfloat16*)(smem + O_W3B);
    float* sWp = (float*)(smem + O_WP);

    // ---------- stage invariant weights + zero Z accum planes ----------
    {
        #pragma unroll 4
        for (int r = 0; r < 32; r++) {
            int i = tid + r * TPB;               // i = j*128 + n
            float v = W2[i];
            __nv_bfloat16 hi = __float2bfloat16_rn(v);
            __nv_bfloat16 lo = __float2bfloat16_rn(v - __bfloat162float(hi));
            int j = i >> 7, n = i & 127;
            sW2B[n*SA + j] = hi;
            sW2B[PLANE_W2/2 + n*SA + j] = lo;
        }
        #pragma unroll
        for (int r = 0; r < 8; r++) {
            int i = tid + r * TPB;               // i = k*32 + c
            float v = W3[i];
            __nv_bfloat16 hi = __float2bfloat16_rn(v);
            __nv_bfloat16 lo = __float2bfloat16_rn(v - __bfloat162float(hi));
            int k = i >> 5, c = i & 31;
            sW3B[c*SA + k] = hi;
            sW3B[PLANE_W3/2 + c*SA + k] = lo;
        }
        if (tid < 128) ((float4*)(smem + O_W1))[tid] = ((const float4*)W1)[tid];
        if (tid >= 128 && tid < 160) ((float4*)(smem + O_B1))[tid-128] = ((const float4*)b1)[tid-128];
        if (tid >= 160 && tid < 192) ((float4*)(smem + O_B2))[tid-160] = ((const float4*)b2)[tid-160];
        if (tid >= 192 && tid < 200) ((float4*)(smem + O_B3))[tid-192] = ((const float4*)b3)[tid-192];
        for (int i = tid; i < 4096; i += TPB) {
            int c = i >> 7, pp = i & 127;
            float pos = (float)pp / 127.0f * 20.0f;
            int idx = (int)pos; if (idx > 20) idx = 20;
            float frac = pos - (float)idx;
            int idx2 = idx + 1; if (idx2 > 20) idx2 = 20;
            sWp[i] = (1.0f - frac) * pwm[c*21 + idx] + frac * pwm[c*21 + idx2];
        }
        float* zz = (float*)(smem + O_ZP0);
        for (int i = tid; i < 2*4224; i += TPB) zz[i] = 0.0f;   // both planes contiguous
    }

    const int wm = wid >> 2, wn = wid & 3;
    const int m0 = wm * 32, n0 = wn * 32;

    // ldmatrix per-lane geometry (verified passing since R11)
    const int aRow = (mi & 1) * 8 + l8;
    const int aCol = (mi >> 1) * 8;
    const int bRow = ((mi >> 1) & 1) * 8 + l8;
    const int bCol = (mi & 1) * 8;

    __syncthreads();

    // ---------- persistent W3 B-fragments ----------
    uint32_t b3h[2][4][2], b3l[2][4][2];         // [kf][chf][reg]
    {
        #pragma unroll
        for (int kf = 0; kf < 2; kf++) {
            #pragma unroll
            for (int cp = 0; cp < 2; cp++) {
                uint32_t addrh = sb + O_W3B + (uint32_t)((cp*16 + bRow)*SA + n0 + kf*16 + bCol)*2;
                uint32_t r0,r1,r2,r3;
                LDSM4(r0,r1,r2,r3, addrh);
                b3h[kf][2*cp][0]=r0; b3h[kf][2*cp][1]=r1; b3h[kf][2*cp+1][0]=r2; b3h[kf][2*cp+1][1]=r3;
                LDSM4(r0,r1,r2,r3, addrh + PLANE_W3);
                b3l[kf][2*cp][0]=r0; b3l[kf][2*cp][1]=r1; b3l[kf][2*cp+1][0]=r2; b3l[kf][2*cp+1][1]=r3;
            }
        }
    }

    // ---------- pool lambda: sort + weighted sum + direct output for set sp ----------
    auto do_pool = [&](int sp) {
        const int bprev = blockIdx.x * SETS + sp;
        float* zp = (float*)(smem + ((sp & 1) ? O_ZP1 : O_ZP0));
        const float* sb3 = (const float*)(smem + O_B3);
        float pooled[2];
        #pragma unroll
        for (int cc = 0; cc < 2; cc++) {
            const int c = wid * 2 + cc;
            const float bias = sb3[c];
            float v[4];
            #pragma unroll
            for (int r = 0; r < 4; r++) {
                int p = r*32 + lane;
                v[r] = zp[c*132 + p] + bias;
                zp[c*132 + p] = 0.0f;            // re-zero for set sp+2
            }
            #pragma unroll
            for (int k = 2; k <= 128; k <<= 1) {
                #pragma unroll
                for (int st = 64; st >= 1; st >>= 1) {
                    if (st >= k) continue;
                    if (st < 32) {
                        const bool lower = ((lane & st) == 0);
                        #pragma unroll
                        for (int r = 0; r < 4; r++) {
                            float o = __shfl_xor_sync(0xffffffffu, v[r], st);
                            bool up = (((r*32 + lane) & k) == 0);
                            bool tmin = (up == lower);
                            float mn = fminf(v[r], o), mx = fmaxf(v[r], o);
                            v[r] = tmin ? mn : mx;
                        }
                    } else if (st == 32) {
                        #pragma unroll
                        for (int ra = 0; ra < 4; ra += 2) {
                            bool up = (((ra*32) & k) == 0);
                            float mn = fminf(v[ra], v[ra+1]), mx = fmaxf(v[ra], v[ra+1]);
                            v[ra]   = up ? mn : mx;
                            v[ra+1] = up ? mx : mn;
                        }
                    } else {
                        #pragma unroll
                        for (int ra = 0; ra < 2; ra++) {
                            float mn = fminf(v[ra], v[ra+2]), mx = fmaxf(v[ra], v[ra+2]);
                            v[ra]   = mn;
                            v[ra+2] = mx;
                        }
                    }
                }
            }
            const float* wc = sWp + c * 128;
            float sum = v[0] * wc[127 - lane]
                      + v[1] * wc[95  - lane]
                      + v[2] * wc[63  - lane]
                      + v[3] * wc[31  - lane];
            #pragma unroll
            for (int ofs = 16; ofs > 0; ofs >>= 1)
                sum += __shfl_xor_sync(0xffffffffu, sum, ofs);
            pooled[cc] = sum;
        }
        if (lane == 0) {
            float mu = pooled[0], lv = pooled[1];
            float e  = eps[(size_t)bprev*NLAT + wid];
            float smp = fmaf(e, expf(0.5f * lv), mu);
            out[(size_t)bprev*NLAT + wid] = mu;
            out[(size_t)(NBATCH*NLAT)   + (size_t)bprev*NLAT + wid] = lv;
            out[(size_t)(2*NBATCH*NLAT) + (size_t)bprev*NLAT + wid] = smp;
        }
    };

    // ---------- GEMM lambda: layer2 + epilogue + layer3 + atomic Z accumulate ----------
    auto do_gemm = [&](int s) {
        float cacc[2][4][4];
        #pragma unroll
        for (int i = 0; i < 2; i++)
            #pragma unroll
            for (int j = 0; j < 4; j++)
                #pragma unroll
                for (int r = 0; r < 4; r++) cacc[i][j][r] = 0.0f;
        {
            uint32_t aAddr[2][2], bAddr[2][2];
            #pragma unroll
            for (int pl = 0; pl < 2; pl++) {
                #pragma unroll
                for (int mf = 0; mf < 2; mf++)
                    aAddr[pl][mf] = sb + O_A1 + pl*PLANE_A
                                  + (uint32_t)((m0 + 16*mf + aRow)*SA + aCol)*2;
                #pragma unroll
                for (int np = 0; np < 2; np++)
                    bAddr[pl][np] = sb + O_W2B + pl*PLANE_W2
                                  + (uint32_t)((n0 + np*16 + bRow)*SA + bCol)*2;
            }
            #pragma unroll
            for (int kk = 0; kk < 8; kk++) {
                uint32_t af[2][2][4];
                #pragma unroll
                for (int pl = 0; pl < 2; pl++)
                    #pragma unroll
                    for (int mf = 0; mf < 2; mf++)
                        LDSM4(af[pl][mf][0], af[pl][mf][1], af[pl][mf][2], af[pl][mf][3],
                              aAddr[pl][mf] + kk*32);
                uint32_t bfr[2][4][2];
                #pragma unroll
                for (int pl = 0; pl < 2; pl++)
                    #pragma unroll
                    for (int np = 0; np < 2; np++) {
                        uint32_t r0,r1,r2,r3;
                        LDSM4(r0,r1,r2,r3, bAddr[pl][np] + kk*32);
                        bfr[pl][2*np][0]=r0; bfr[pl][2*np][1]=r1;
                        bfr[pl][2*np+1][0]=r2; bfr[pl][2*np+1][1]=r3;
                    }
                #pragma unroll
                for (int mf = 0; mf < 2; mf++)
                    #pragma unroll
                    for (int nf = 0; nf < 4; nf++) {
                        MMA(cacc[mf][nf], af[0][mf], bfr[0][nf]);   // hi*hi
                        MMA(cacc[mf][nf], af[0][mf], bfr[1][nf]);   // hi*lo
                        MMA(cacc[mf][nf], af[1][mf], bfr[0][nf]);   // lo*hi
                    }
            }
        }
        // epilogue: bias + relu + hi/lo split -> layer3 A frags (registers)
        uint32_t Ah[2][2][4], Al[2][2][4];
        {
            const float* sb2 = (const float*)(smem + O_B2);
            #pragma unroll
            for (int nf = 0; nf < 4; nf++) {
                float bv0 = sb2[n0 + 8*nf + 2*t4];
                float bv1 = sb2[n0 + 8*nf + 2*t4 + 1];
                #pragma unroll
                for (int mf = 0; mf < 2; mf++) {
                    cacc[mf][nf][0] = fmaxf(cacc[mf][nf][0] + bv0, 0.0f);
                    cacc[mf][nf][1] = fmaxf(cacc[mf][nf][1] + bv1, 0.0f);
                    cacc[mf][nf][2] = fmaxf(cacc[mf][nf][2] + bv0, 0.0f);
                    cacc[mf][nf][3] = fmaxf(cacc[mf][nf][3] + bv1, 0.0f);
                }
            }
            #pragma unroll
            for (int mf = 0; mf < 2; mf++)
                #pragma unroll
                for (int kf = 0; kf < 2; kf++) {
                    const float* cL = cacc[mf][2*kf];
                    const float* cH = cacc[mf][2*kf+1];
                    #pragma unroll
                    for (int h = 0; h < 2; h++) {
                        float v0 = cL[2*h], v1 = cL[2*h+1];
                        float w0 = cH[2*h], w1 = cH[2*h+1];
                        __nv_bfloat16 b0 = __float2bfloat16_rn(v0);
                        __nv_bfloat16 b1_ = __float2bfloat16_rn(v1);
                        __nv_bfloat16 b2_ = __float2bfloat16_rn(w0);
                        __nv_bfloat16 b3_ = __float2bfloat16_rn(w1);
                        __nv_bfloat162 p0; p0.x = b0;  p0.y = b1_;
                        __nv_bfloat162 p1; p1.x = b2_; p1.y = b3_;
                        Ah[mf][kf][h]   = *(uint32_t*)&p0;
                        Ah[mf][kf][2+h] = *(uint32_t*)&p1;
                        Al[mf][kf][h]   = pack_bf16x2(v0 - __bfloat162float(b0),
                                                      v1 - __bfloat162float(b1_));
                        Al[mf][kf][2+h] = pack_bf16x2(w0 - __bfloat162float(b2_),
                                                      w1 - __bfloat162float(b3_));
                    }
                }
        }
        // layer3: partial Z over this warp's k-slice
        float zacc[2][4][4];
        #pragma unroll
        for (int i = 0; i < 2; i++)
            #pragma unroll
            for (int j = 0; j < 4; j++)
                #pragma unroll
                for (int r = 0; r < 4; r++) zacc[i][j][r] = 0.0f;
        #pragma unroll
        for (int mf = 0; mf < 2; mf++)
            #pragma unroll
            for (int chf = 0; chf < 4; chf++)
                #pragma unroll
                for (int kf = 0; kf < 2; kf++) {
                    MMA(zacc[mf][chf], Ah[mf][kf], b3h[kf][chf]);
                    MMA(zacc[mf][chf], Ah[mf][kf], b3l[kf][chf]);
                    MMA(zacc[mf][chf], Al[mf][kf], b3h[kf][chf]);
                }
        // accumulate into Z plane (4 warps per address, atomic)
        float* zp = (float*)(smem + ((s & 1) ? O_ZP1 : O_ZP0));
        #pragma unroll
        for (int mf = 0; mf < 2; mf++)
            #pragma unroll
            for (int chf = 0; chf < 4; chf++) {
                int ch = 8*chf + 2*t4;
                int m  = m0 + 16*mf + g;
                atomicAdd(&zp[ch*132 + m],         zacc[mf][chf][0]);
                atomicAdd(&zp[(ch+1)*132 + m],     zacc[mf][chf][1]);
                atomicAdd(&zp[ch*132 + m + 8],     zacc[mf][chf][2]);
                atomicAdd(&zp[(ch+1)*132 + m + 8], zacc[mf][chf][3]);
            }
    };

    for (int s = 0; s < SETS; s++) {
        const int bset = blockIdx.x * SETS + s;
        if (tid < 128) ((float4*)(smem + O_X))[tid] = ((const float4*)(x + (size_t)bset * 512))[tid];
        __syncthreads();   // barrierA: X staged; prev region's A1 reads + ZP zeroing done

        // ---------- layer 1 (scalar) -> A1 hi/lo bf16 [p][j] paired stores ----------
        {
            const float* sX  = (const float*)(smem + O_X);
            const float* sW1 = (const float*)(smem + O_W1);
            const float* sb1 = (const float*)(smem + O_B1);
            const int p = tid >> 2, kg = tid & 3;
            const int j0 = kg * 32;
            float x0 = sX[p*4+0], x1 = sX[p*4+1], x2 = sX[p*4+2], x3 = sX[p*4+3];
            uint32_t* hiw = (uint32_t*)(smem + O_A1) + p*(SA/2) + kg*16;
            uint32_t* low = (uint32_t*)(smem + O_A1 + PLANE_A) + p*(SA/2) + kg*16;
            #pragma unroll 4
            for (int tt = 0; tt < 16; tt++) {
                int j = j0 + 2*tt;
                float a0 = sb1[j], a1 = sb1[j+1];
                a0 = fmaf(x0, sW1[j],       a0);  a1 = fmaf(x0, sW1[j+1],       a1);
                a0 = fmaf(x1, sW1[128 + j], a0);  a1 = fmaf(x1, sW1[128 + j+1], a1);
                a0 = fmaf(x2, sW1[256 + j], a0);  a1 = fmaf(x2, sW1[256 + j+1], a1);
                a0 = fmaf(x3, sW1[384 + j], a0);  a1 = fmaf(x3, sW1[384 + j+1], a1);
                a0 = fmaxf(a0, 0.0f);  a1 = fmaxf(a1, 0.0f);
                __nv_bfloat16 h0 = __float2bfloat16_rn(a0);
                __nv_bfloat16 h1 = __float2bfloat16_rn(a1);
                __nv_bfloat162 hp; hp.x = h0; hp.y = h1;
                hiw[tt] = *(uint32_t*)&hp;
                low[tt] = pack_bf16x2(a0 - __bfloat162float(h0), a1 - __bfloat162float(h1));
            }
        }
        __syncthreads();   // barrier2: A1 visible; X free; prev ZP accumulation complete

        // ---------- overlapped region: GEMM(s) + pool(s-1), parity-ordered ----------
        if (wid & 1) {
            do_gemm(s);
            if (s > 0) do_pool(s - 1);
        } else {
            if (s > 0) do_pool(s - 1);
            do_gemm(s);
        }
    }
    __syncthreads();
    do_pool(SETS - 1);
}

extern "C" void kernel_launch(void* const* d_in, const int* in_sizes, int n_in,
                              void* d_out, int out_size) {
    const float* x   = (const float*)d_in[0];
    const float* W1  = (const float*)d_in[1];
    const float* b1  = (const float*)d_in[2];
    const float* W2  = (const float*)d_in[3];
    const float* b2  = (const float*)d_in[4];
    const float* W3  = (const float*)d_in[5];
    const float* b3  = (const float*)d_in[6];
    const float* pwm = (const float*)d_in[7];
    const float* eps = (const float*)d_in[8];
    float* out = (float*)d_out;

    cudaFuncSetAttribute(enc_kernel, cudaFuncAttributeMaxDynamicSharedMemorySize, SMEM_BYTES);
    enc_kernel<<<GRID, TPB, SMEM_BYTES>>>(x, W1, b1, W2, b2, W3, b3, pwm, eps, out);
}

// round 14
// speedup vs baseline: 1.5812x; 1.5812x over previous
#include <cuda_runtime.h>
#include <cuda_bf16.h>
#include <cstdint>

#define NBATCH 8192
#define SETS   4
#define GRID   (NBATCH/SETS)
#define TPB    1024
#define NLAT   16

#define SA 136            // halfword stride for A1/W2/W3 [.][k] bf16 arrays
#define PLANE_A  34816    // 128*136*2 bytes
#define PLANE_W2 34816
#define PLANE_W3 8704     // 32*136*2
#define PLANE_X  6144     // 128*24*2

// ---------------- shared memory layout (bytes) ----------------
#define O_W2B 0           // W2 as B: [n=128][k=136] bf16, hi+lo planes (69632)
#define O_W3B 69632       // W3 as B: [n=32][k=136] bf16, hi+lo planes (17408)
#define O_A1  87040       // A: [m=128][k=136] bf16, hi+lo planes (69632)
#define O_ZP  87040       // alias: Zpart[4][32][132] f32 = 67584
#define O_WP  156672      // fspool weights f32 [32][128] (16384)
#define O_XS  173056      // X bf16 [128][24] hi+lo planes (12288)
#define O_W1B 185344      // [W1T|b1] bf16 [128][24] hi+lo planes (12288)
#define O_B2  197632      // 512
#define O_B3  198144      // 128
#define O_PL  198272      // 128
#define SMEM_BYTES 198400

__device__ __forceinline__ uint32_t cvta_smem(const void* p) {
    uint32_t a;
    asm("{ .reg .u64 t; cvta.to.shared.u64 t, %1; cvt.u32.u64 %0, t; }" : "=r"(a) : "l"(p));
    return a;
}
__device__ __forceinline__ uint32_t pack_bf16x2(float lo, float hi) {
    __nv_bfloat162 t;
    t.x = __float2bfloat16_rn(lo);
    t.y = __float2bfloat16_rn(hi);
    return *(uint32_t*)&t;
}

#define LDSM4(R0,R1,R2,R3,ADDR) \
    asm volatile("ldmatrix.sync.aligned.m8n8.x4.shared.b16 {%0,%1,%2,%3}, [%4];" \
        : "=r"(R0),"=r"(R1),"=r"(R2),"=r"(R3) : "r"(ADDR) : "memory")

#define MMA(C,A,B) \
    asm volatile("mma.sync.aligned.m16n8k16.row.col.f32.bf16.bf16.f32 " \
        "{%0,%1,%2,%3}, {%4,%5,%6,%7}, {%8,%9}, {%0,%1,%2,%3};" \
        : "+f"((C)[0]),"+f"((C)[1]),"+f"((C)[2]),"+f"((C)[3]) \
        : "r"((A)[0]),"r"((A)[1]),"r"((A)[2]),"r"((A)[3]), "r"((B)[0]),"r"((B)[1]))

__global__ __launch_bounds__(TPB, 1)
void enc_kernel(const float* __restrict__ x,  const float* __restrict__ W1,
                const float* __restrict__ b1, const float* __restrict__ W2,
                const float* __restrict__ b2, const float* __restrict__ W3,
                const float* __restrict__ b3, const float* __restrict__ pwm,
                const float* __restrict__ eps, float* __restrict__ out)
{
    extern __shared__ __align__(1024) char smem[];
    const uint32_t sb = cvta_smem(smem);
    const int tid = threadIdx.x;
    const int wid = tid >> 5, lane = tid & 31;
    const int g = lane >> 2, t4 = lane & 3;
    const int l8 = lane & 7, mi = lane >> 3;

    __nv_bfloat16* sW2B = (__nv_bfloat16*)(smem + O_W2B);
    __nv_bfloat16* sW3B = (__nv_bfloat16*)(smem + O_W3B);
    float* sWp = (float*)(smem + O_WP);

    // ---------- stage invariant weights ----------
    {
        #pragma unroll 4
        for (int r = 0; r < 16; r++) {
            int i = tid + r * TPB;               // i = j*128 + n
            float v = W2[i];
            __nv_bfloat16 hi = __float2bfloat16_rn(v);
            __nv_bfloat16 lo = __float2bfloat16_rn(v - __bfloat162float(hi));
            int j = i >> 7, n = i & 127;
            sW2B[n*SA + j] = hi;
            sW2B[PLANE_W2/2 + n*SA + j] = lo;
        }
        #pragma unroll
        for (int r = 0; r < 4; r++) {
            int i = tid + r * TPB;               // i = k*32 + c
            float v = W3[i];
            __nv_bfloat16 hi = __float2bfloat16_rn(v);
            __nv_bfloat16 lo = __float2bfloat16_rn(v - __bfloat162float(hi));
            int k = i >> 5, c = i & 31;
            sW3B[c*SA + k] = hi;
            sW3B[PLANE_W3/2 + c*SA + k] = lo;
        }
        // W1B: row j, cols 0..3 = W1[f][j], col 4 = b1[j], rest 0. Zero XS pad too.
        if (tid < 128) {
            int j = tid;
            uint32_t* wh = (uint32_t*)(smem + O_W1B) + j*12;
            uint32_t* wl = (uint32_t*)(smem + O_W1B + PLANE_X) + j*12;
            uint32_t* xh = (uint32_t*)(smem + O_XS)  + j*12;
            uint32_t* xl = (uint32_t*)(smem + O_XS + PLANE_X) + j*12;
            #pragma unroll
            for (int q = 0; q < 12; q++) { wh[q] = 0u; wl[q] = 0u; xh[q] = 0u; xl[q] = 0u; }
            float w0 = W1[j], w1 = W1[128 + j], w2_ = W1[256 + j], w3_ = W1[384 + j];
            float bb = b1[j];
            __nv_bfloat16 h0 = __float2bfloat16_rn(w0), h1 = __float2bfloat16_rn(w1);
            __nv_bfloat16 h2 = __float2bfloat16_rn(w2_), h3 = __float2bfloat16_rn(w3_);
            __nv_bfloat16 hb = __float2bfloat16_rn(bb);
            __nv_bfloat162 p01; p01.x = h0; p01.y = h1;
            __nv_bfloat162 p23; p23.x = h2; p23.y = h3;
            __nv_bfloat162 pb;  pb.x  = hb; pb.y  = __float2bfloat16_rn(0.0f);
            wh[0] = *(uint32_t*)&p01;
            wh[1] = *(uint32_t*)&p23;
            wh[2] = *(uint32_t*)&pb;
            wl[0] = pack_bf16x2(w0 - __bfloat162float(h0), w1 - __bfloat162float(h1));
            wl[1] = pack_bf16x2(w2_ - __bfloat162float(h2), w3_ - __bfloat162float(h3));
            wl[2] = pack_bf16x2(bb - __bfloat162float(hb), 0.0f);
        }
        if (tid >= 160 && tid < 192) ((float4*)(smem + O_B2))[tid-160] = ((const float4*)b2)[tid-160];
        if (tid >= 192 && tid < 200) ((float4*)(smem + O_B3))[tid-192] = ((const float4*)b3)[tid-192];
        #pragma unroll
        for (int r = 0; r < 4; r++) {
            int i = tid + r * TPB;
            int c = i >> 7, pp = i & 127;
            float pos = (float)pp / 127.0f * 20.0f;
            int idx = (int)pos; if (idx > 20) idx = 20;
            float frac = pos - (float)idx;
            int idx2 = idx + 1; if (idx2 > 20) idx2 = 20;
            sWp[i] = (1.0f - frac) * pwm[c*21 + idx] + frac * pwm[c*21 + idx2];
        }
    }
    __syncthreads();

    const int wm = wid >> 2, wn = wid & 3;       // 8 x 4 warp grid
    const int m0 = wm * 16, n0 = wn * 32;

    // ldmatrix per-lane geometry (verified passing since R11)
    const int aRow = (mi & 1) * 8 + l8;
    const int aCol = (mi >> 1) * 8;
    const int bRow = ((mi >> 1) & 1) * 8 + l8;
    const int bCol = (mi & 1) * 8;

    for (int s = 0; s < SETS; s++) {
        const int bset = blockIdx.x * SETS + s;

        // ---------- stage X (hi/lo bf16, with constant-1 bias column) ----------
        if (tid < 128) {
            float4 xv = ((const float4*)(x + (size_t)bset * 512))[tid];
            uint32_t* xh = (uint32_t*)(smem + O_XS) + tid*12;
            uint32_t* xl = (uint32_t*)(smem + O_XS + PLANE_X) + tid*12;
            __nv_bfloat16 h0 = __float2bfloat16_rn(xv.x), h1 = __float2bfloat16_rn(xv.y);
            __nv_bfloat16 h2 = __float2bfloat16_rn(xv.z), h3 = __float2bfloat16_rn(xv.w);
            __nv_bfloat162 p01; p01.x = h0; p01.y = h1;
            __nv_bfloat162 p23; p23.x = h2; p23.y = h3;
            __nv_bfloat162 pb;  pb.x  = __float2bfloat16_rn(1.0f); pb.y = __float2bfloat16_rn(0.0f);
            xh[0] = *(uint32_t*)&p01;
            xh[1] = *(uint32_t*)&p23;
            xh[2] = *(uint32_t*)&pb;
            xl[0] = pack_bf16x2(xv.x - __bfloat162float(h0), xv.y - __bfloat162float(h1));
            xl[1] = pack_bf16x2(xv.z - __bfloat162float(h2), xv.w - __bfloat162float(h3));
            xl[2] = 0u;
        }
        __syncthreads();   // X staged; prev set's Zpart/sPl reads done (A1 region free)

        // ---------- layer 1 via mma: H1 tile [16m x 32j] per warp ----------
        {
            uint32_t w1h[4][2], w1l[4][2];
            #pragma unroll
            for (int np = 0; np < 2; np++) {
                uint32_t addrh = sb + O_W1B + (uint32_t)((n0 + np*16 + bRow)*24 + bCol)*2;
                uint32_t r0,r1,r2,r3;
                LDSM4(r0,r1,r2,r3, addrh);
                w1h[2*np][0]=r0; w1h[2*np][1]=r1; w1h[2*np+1][0]=r2; w1h[2*np+1][1]=r3;
                LDSM4(r0,r1,r2,r3, addrh + PLANE_X);
                w1l[2*np][0]=r0; w1l[2*np][1]=r1; w1l[2*np+1][0]=r2; w1l[2*np+1][1]=r3;
            }
            uint32_t xfh[4], xfl[4];
            {
                uint32_t ah = sb + O_XS + (uint32_t)((m0 + aRow)*24 + aCol)*2;
                LDSM4(xfh[0], xfh[1], xfh[2], xfh[3], ah);
                LDSM4(xfl[0], xfl[1], xfl[2], xfl[3], ah + PLANE_X);
            }
            float c1[4][4];
            #pragma unroll
            for (int j = 0; j < 4; j++)
                #pragma unroll
                for (int r = 0; r < 4; r++) c1[j][r] = 0.0f;
            #pragma unroll
            for (int nf = 0; nf < 4; nf++) {
                MMA(c1[nf], xfh, w1h[nf]);
                MMA(c1[nf], xfh, w1l[nf]);
                MMA(c1[nf], xfl, w1h[nf]);
            }
            uint32_t* a1h = (uint32_t*)(smem + O_A1);
            uint32_t* a1l = (uint32_t*)(smem + O_A1 + PLANE_A);
            #pragma unroll
            for (int nf = 0; nf < 4; nf++)
                #pragma unroll
                for (int h = 0; h < 2; h++) {
                    float v0 = fmaxf(c1[nf][2*h],   0.0f);
                    float v1 = fmaxf(c1[nf][2*h+1], 0.0f);
                    __nv_bfloat16 bh0 = __float2bfloat16_rn(v0);
                    __nv_bfloat16 bh1 = __float2bfloat16_rn(v1);
                    __nv_bfloat162 ph; ph.x = bh0; ph.y = bh1;
                    int m = m0 + g + 8*h;
                    int w = m*(SA/2) + (n0 >> 1) + 4*nf + t4;
                    a1h[w] = *(uint32_t*)&ph;
                    a1l[w] = pack_bf16x2(v0 - __bfloat162float(bh0),
                                         v1 - __bfloat162float(bh1));
                }
        }
        __syncthreads();

        // ---------- layer 2: C[16x32] per warp via mma.sync, 8 k-steps ----------
        float cacc[4][4];
        #pragma unroll
        for (int j = 0; j < 4; j++)
            #pragma unroll
            for (int r = 0; r < 4; r++) cacc[j][r] = 0.0f;
        {
            uint32_t aAddr[2], bAddr[2][2];
            #pragma unroll
            for (int pl = 0; pl < 2; pl++) {
                aAddr[pl] = sb + O_A1 + pl*PLANE_A + (uint32_t)((m0 + aRow)*SA + aCol)*2;
                #pragma unroll
                for (int np = 0; np < 2; np++)
                    bAddr[pl][np] = sb + O_W2B + pl*PLANE_W2
                                  + (uint32_t)((n0 + np*16 + bRow)*SA + bCol)*2;
            }
            #pragma unroll
            for (int kk = 0; kk < 8; kk++) {
                uint32_t af[2][4];
                #pragma unroll
                for (int pl = 0; pl < 2; pl++)
                    LDSM4(af[pl][0], af[pl][1], af[pl][2], af[pl][3], aAddr[pl] + kk*32);
                uint32_t bfr[2][4][2];
                #pragma unroll
                for (int pl = 0; pl < 2; pl++)
                    #pragma unroll
                    for (int np = 0; np < 2; np++) {
                        uint32_t r0,r1,r2,r3;
                        LDSM4(r0,r1,r2,r3, bAddr[pl][np] + kk*32);
                        bfr[pl][2*np][0]=r0; bfr[pl][2*np][1]=r1;
                        bfr[pl][2*np+1][0]=r2; bfr[pl][2*np+1][1]=r3;
                    }
                #pragma unroll
                for (int nf = 0; nf < 4; nf++) {
                    MMA(cacc[nf], af[0], bfr[0][nf]);   // hi*hi
                    MMA(cacc[nf], af[0], bfr[1][nf]);   // hi*lo
                    MMA(cacc[nf], af[1], bfr[0][nf]);   // lo*hi
                }
            }
        }

        // ---------- epilogue in registers: bias + relu + hi/lo split ----------
        uint32_t Ah[2][4], Al[2][4];               // [kf][reg]
        {
            const float* sb2 = (const float*)(smem + O_B2);
            #pragma unroll
            for (int nf = 0; nf < 4; nf++) {
                float bv0 = sb2[n0 + 8*nf + 2*t4];
                float bv1 = sb2[n0 + 8*nf + 2*t4 + 1];
                cacc[nf][0] = fmaxf(cacc[nf][0] + bv0, 0.0f);
                cacc[nf][1] = fmaxf(cacc[nf][1] + bv1, 0.0f);
                cacc[nf][2] = fmaxf(cacc[nf][2] + bv0, 0.0f);
                cacc[nf][3] = fmaxf(cacc[nf][3] + bv1, 0.0f);
            }
            #pragma unroll
            for (int kf = 0; kf < 2; kf++) {
                const float* cL = cacc[2*kf];
                const float* cH = cacc[2*kf+1];
                #pragma unroll
                for (int h = 0; h < 2; h++) {
                    float v0 = cL[2*h], v1 = cL[2*h+1];
                    float w0 = cH[2*h], w1 = cH[2*h+1];
                    __nv_bfloat16 b0 = __float2bfloat16_rn(v0);
                    __nv_bfloat16 b1_ = __float2bfloat16_rn(v1);
                    __nv_bfloat16 b2_ = __float2bfloat16_rn(w0);
                    __nv_bfloat16 b3_ = __float2bfloat16_rn(w1);
                    __nv_bfloat162 p0; p0.x = b0;  p0.y = b1_;
                    __nv_bfloat162 p1; p1.x = b2_; p1.y = b3_;
                    Ah[kf][h]   = *(uint32_t*)&p0;
                    Ah[kf][2+h] = *(uint32_t*)&p1;
                    Al[kf][h]   = pack_bf16x2(v0 - __bfloat162float(b0),
                                              v1 - __bfloat162float(b1_));
                    Al[kf][2+h] = pack_bf16x2(w0 - __bfloat162float(b2_),
                                              w1 - __bfloat162float(b3_));
                }
            }
        }

        // ---------- layer 3: partial Z[16m x 32ch] over this warp's k-slice ----------
        float zacc[4][4];
        #pragma unroll
        for (int j = 0; j < 4; j++)
            #pragma unroll
            for (int r = 0; r < 4; r++) zacc[j][r] = 0.0f;
        #pragma unroll
        for (int cp = 0; cp < 2; cp++) {           // chf pairs {0,1},{2,3}
            uint32_t b3hF[2][2], b3lF[2][2];
            #pragma unroll
            for (int kf = 0; kf < 2; kf++) {
                uint32_t addrh = sb + O_W3B + (uint32_t)((cp*16 + bRow)*SA + n0 + kf*16 + bCol)*2;
                uint32_t r0,r1,r2,r3;
                LDSM4(r0,r1,r2,r3, addrh);
                // x4 layout: frag (cp*2) regs {r0,r1}, frag (cp*2+1) regs {r2,r3} per kf
                b3hF[kf][0]=r0; b3hF[kf][1]=r1;
                uint32_t q0,q1,q2,q3;
                LDSM4(q0,q1,q2,q3, addrh + PLANE_W3);
                b3lF[kf][0]=q0; b3lF[kf][1]=q1;
                // second n-frag of this pair
                uint32_t h2[2] = {r2, r3}, l2[2] = {q2, q3};
                #pragma unroll
                for (int z = 0; z < 1; z++) { }    // (placeholder, regs consumed below)
                // chf = 2*cp uses {r0,r1}; chf = 2*cp+1 uses {r2,r3}
                uint32_t bh0[2] = {r0, r1}, bl0[2] = {q0, q1};
                MMA(zacc[2*cp],   Ah[kf], bh0);
                MMA(zacc[2*cp],   Ah[kf], bl0);
                MMA(zacc[2*cp],   Al[kf], bh0);
                MMA(zacc[2*cp+1], Ah[kf], h2);
                MMA(zacc[2*cp+1], Ah[kf], l2);
                MMA(zacc[2*cp+1], Al[kf], h2);
            }
            (void)b3hF; (void)b3lF;
        }

        __syncthreads();   // ldmatrix reads of A1/W2 done -> Zpart may alias A1

        // ---------- store partial Z: Zpart[wn][ch][132] ----------
        {
            float* zp = (float*)(smem + O_ZP) + wn * 4224;
            #pragma unroll
            for (int chf = 0; chf < 4; chf++) {
                int ch = 8*chf + 2*t4;
                int m  = m0 + g;
                zp[ch*132 + m]         = zacc[chf][0];
                zp[(ch+1)*132 + m]     = zacc[chf][1];
                zp[ch*132 + m + 8]     = zacc[chf][2];
                zp[(ch+1)*132 + m + 8] = zacc[chf][3];
            }
        }
        __syncthreads();

        // ---------- bitonic sorted-dot pool (1 channel per warp) ----------
        {
            const float* sb3 = (const float*)(smem + O_B3);
            const float* zp0 = (const float*)(smem + O_ZP);
            float* sPl = (float*)(smem + O_PL);
            const int c = wid;
            const float bias = sb3[c];
            float v[4];
            #pragma unroll
            for (int r = 0; r < 4; r++) {
                int p = r*32 + lane;
                v[r] = zp0[c*132 + p] + zp0[4224 + c*132 + p]
                     + zp0[8448 + c*132 + p] + zp0[12672 + c*132 + p] + bias;
            }
            #pragma unroll
            for (int k = 2; k <= 128; k <<= 1) {
                #pragma unroll
                for (int st = 64; st >= 1; st >>= 1) {
                    if (st >= k) continue;
                    if (st < 32) {
                        const bool lower = ((lane & st) == 0);
                        #pragma unroll
                        for (int r = 0; r < 4; r++) {
                            float o = __shfl_xor_sync(0xffffffffu, v[r], st);
                            bool up = (((r*32 + lane) & k) == 0);
                            bool tmin = (up == lower);
                            float mn = fminf(v[r], o), mx = fmaxf(v[r], o);
                            v[r] = tmin ? mn : mx;
                        }
                    } else if (st == 32) {
                        #pragma unroll
                        for (int ra = 0; ra < 4; ra += 2) {
                            bool up = (((ra*32) & k) == 0);
                            float mn = fminf(v[ra], v[ra+1]), mx = fmaxf(v[ra], v[ra+1]);
                            v[ra]   = up ? mn : mx;
                            v[ra+1] = up ? mx : mn;
                        }
                    } else {
                        #pragma unroll
                        for (int ra = 0; ra < 2; ra++) {
                            float mn = fminf(v[ra], v[ra+2]), mx = fmaxf(v[ra], v[ra+2]);
                            v[ra]   = mn;
                            v[ra+2] = mx;
                        }
                    }
                }
            }
            const float* wc = sWp + c * 128;
            float sum = v[0] * wc[127 - lane]
                      + v[1] * wc[95  - lane]
                      + v[2] * wc[63  - lane]
                      + v[3] * wc[31  - lane];
            #pragma unroll
            for (int ofs = 16; ofs > 0; ofs >>= 1)
                sum += __shfl_xor_sync(0xffffffffu, sum, ofs);
            if (lane == 0) sPl[c] = sum;
        }
        __syncthreads();

        // ---------- reparameterize + write ----------
        if (tid < NLAT) {
            const float* sPl = (const float*)(smem + O_PL);
            float mu = sPl[2*tid];
            float lv = sPl[2*tid + 1];
            float e  = eps[(size_t)bset*NLAT + tid];
            float smp = fmaf(e, expf(0.5f * lv), mu);
            out[(size_t)bset*NLAT + tid] = mu;
            out[(size_t)(NBATCH*NLAT)   + (size_t)bset*NLAT + tid] = lv;
            out[(size_t)(2*NBATCH*NLAT) + (size_t)bset*NLAT + tid] = smp;
        }
        __syncthreads();   // sPl/Zpart reads done before next set overwrites
    }
}

extern "C" void kernel_launch(void* const* d_in, const int* in_sizes, int n_in,
                              void* d_out, int out_size) {
    const float* x   = (const float*)d_in[0];
    const float* W1  = (const float*)d_in[1];
    const float* b1  = (const float*)d_in[2];
    const float* W2  = (const float*)d_in[3];
    const float* b2  = (const float*)d_in[4];
    const float* W3  = (const float*)d_in[5];
    const float* b3  = (const float*)d_in[6];
    const float* pwm = (const float*)d_in[7];
    const float* eps = (const float*)d_in[8];
    float* out = (float*)d_out;

    cudaFuncSetAttribute(enc_kernel, cudaFuncAttributeMaxDynamicSharedMemorySize, SMEM_BYTES);
    enc_kernel<<<GRID, TPB, SMEM_BYTES>>>(x, W1, b1, W2, b2, W3, b3, pwm, eps, out);
}

// round 15
// speedup vs baseline: 1.6164x; 1.0223x over previous
#include <cuda_runtime.h>
#include <cuda_bf16.h>
#include <cstdint>

#define NBATCH 8192
#define SETS   8
#define GRID   (NBATCH/SETS)
#define TPB    1024
#define NLAT   16

#define SA 136            // halfword stride for A1/W2/W3 [.][k] bf16 arrays
#define PLANE_A  34816    // 128*136*2 bytes
#define PLANE_W2 34816
#define PLANE_W3 8704     // 32*136*2
#define PLANE_X  6144     // 128*24*2

// ---------------- shared memory layout (bytes) ----------------
#define O_W2B 0           // W2 as B: [n=128][k=136] bf16, hi+lo planes (69632)
#define O_W3B 69632       // W3 as B: [n=32][k=136] bf16, hi+lo planes (17408)
#define O_A1  87040       // A: [m=128][k=136] bf16, hi+lo planes (69632)
#define O_ZP  87040       // alias: Zpart[4][32][132] f32 = 67584
#define O_WP  156672      // fspool weights f32 [32][128] (16384)
#define O_XS  173056      // X bf16 [128][24] hi+lo planes (12288)
#define O_W1B 185344      // [W1T|b1] bf16 [128][24] hi+lo planes (12288)
#define O_B2  197632      // 512
#define O_B3  198144      // 128
#define O_PL  198272      // 128
#define SMEM_BYTES 198400

__device__ __forceinline__ uint32_t cvta_smem(const void* p) {
    uint32_t a;
    asm("{ .reg .u64 t; cvta.to.shared.u64 t, %1; cvt.u32.u64 %0, t; }" : "=r"(a) : "l"(p));
    return a;
}
__device__ __forceinline__ uint32_t pack_bf16x2(float lo, float hi) {
    __nv_bfloat162 t;
    t.x = __float2bfloat16_rn(lo);
    t.y = __float2bfloat16_rn(hi);
    return *(uint32_t*)&t;
}

#define LDSM4(R0,R1,R2,R3,ADDR) \
    asm volatile("ldmatrix.sync.aligned.m8n8.x4.shared.b16 {%0,%1,%2,%3}, [%4];" \
        : "=r"(R0),"=r"(R1),"=r"(R2),"=r"(R3) : "r"(ADDR) : "memory")

#define MMA(C,A,B) \
    asm volatile("mma.sync.aligned.m16n8k16.row.col.f32.bf16.bf16.f32 " \
        "{%0,%1,%2,%3}, {%4,%5,%6,%7}, {%8,%9}, {%0,%1,%2,%3};" \
        : "+f"((C)[0]),"+f"((C)[1]),"+f"((C)[2]),"+f"((C)[3]) \
        : "r"((A)[0]),"r"((A)[1]),"r"((A)[2]),"r"((A)[3]), "r"((B)[0]),"r"((B)[1]))

__global__ __launch_bounds__(TPB, 1)
void enc_kernel(const float* __restrict__ x,  const float* __restrict__ W1,
                const float* __restrict__ b1, const float* __restrict__ W2,
                const float* __restrict__ b2, const float* __restrict__ W3,
                const float* __restrict__ b3, const float* __restrict__ pwm,
                const float* __restrict__ eps, float* __restrict__ out)
{
    extern __shared__ __align__(1024) char smem[];
    const uint32_t sb = cvta_smem(smem);
    const int tid = threadIdx.x;
    const int wid = tid >> 5, lane = tid & 31;
    const int g = lane >> 2, t4 = lane & 3;
    const int l8 = lane & 7, mi = lane >> 3;

    __nv_bfloat16* sW2B = (__nv_bfloat16*)(smem + O_W2B);
    __nv_bfloat16* sW3B = (__nv_bfloat16*)(smem + O_W3B);
    float* sWp = (float*)(smem + O_WP);

    // ---------- stage invariant weights ----------
    {
        #pragma unroll 4
        for (int r = 0; r < 16; r++) {
            int i = tid + r * TPB;               // i = j*128 + n
            float v = W2[i];
            __nv_bfloat16 hi = __float2bfloat16_rn(v);
            __nv_bfloat16 lo = __float2bfloat16_rn(v - __bfloat162float(hi));
            int j = i >> 7, n = i & 127;
            sW2B[n*SA + j] = hi;
            sW2B[PLANE_W2/2 + n*SA + j] = lo;
        }
        #pragma unroll
        for (int r = 0; r < 4; r++) {
            int i = tid + r * TPB;               // i = k*32 + c
            float v = W3[i];
            __nv_bfloat16 hi = __float2bfloat16_rn(v);
            __nv_bfloat16 lo = __float2bfloat16_rn(v - __bfloat162float(hi));
            int k = i >> 5, c = i & 31;
            sW3B[c*SA + k] = hi;
            sW3B[PLANE_W3/2 + c*SA + k] = lo;
        }
        // W1B: row j, cols 0..3 = W1[f][j], col 4 = b1[j], rest 0. Zero XS pad too.
        if (tid < 128) {
            int j = tid;
            uint32_t* wh = (uint32_t*)(smem + O_W1B) + j*12;
            uint32_t* wl = (uint32_t*)(smem + O_W1B + PLANE_X) + j*12;
            uint32_t* xh = (uint32_t*)(smem + O_XS)  + j*12;
            uint32_t* xl = (uint32_t*)(smem + O_XS + PLANE_X) + j*12;
            #pragma unroll
            for (int q = 0; q < 12; q++) { wh[q] = 0u; wl[q] = 0u; xh[q] = 0u; xl[q] = 0u; }
            float w0 = W1[j], w1 = W1[128 + j], w2_ = W1[256 + j], w3_ = W1[384 + j];
            float bb = b1[j];
            __nv_bfloat16 h0 = __float2bfloat16_rn(w0), h1 = __float2bfloat16_rn(w1);
            __nv_bfloat16 h2 = __float2bfloat16_rn(w2_), h3 = __float2bfloat16_rn(w3_);
            __nv_bfloat16 hb = __float2bfloat16_rn(bb);
            __nv_bfloat162 p01; p01.x = h0; p01.y = h1;
            __nv_bfloat162 p23; p23.x = h2; p23.y = h3;
            __nv_bfloat162 pb;  pb.x  = hb; pb.y  = __float2bfloat16_rn(0.0f);
            wh[0] = *(uint32_t*)&p01;
            wh[1] = *(uint32_t*)&p23;
            wh[2] = *(uint32_t*)&pb;
            wl[0] = pack_bf16x2(w0 - __bfloat162float(h0), w1 - __bfloat162float(h1));
            wl[1] = pack_bf16x2(w2_ - __bfloat162float(h2), w3_ - __bfloat162float(h3));
            wl[2] = pack_bf16x2(bb - __bfloat162float(hb), 0.0f);
        }
        if (tid >= 160 && tid < 192) ((float4*)(smem + O_B2))[tid-160] = ((const float4*)b2)[tid-160];
        if (tid >= 192 && tid < 200) ((float4*)(smem + O_B3))[tid-192] = ((const float4*)b3)[tid-192];
        #pragma unroll
        for (int r = 0; r < 4; r++) {
            int i = tid + r * TPB;
            int c = i >> 7, pp = i & 127;
            float pos = (float)pp / 127.0f * 20.0f;
            int idx = (int)pos; if (idx > 20) idx = 20;
            float frac = pos - (float)idx;
            int idx2 = idx + 1; if (idx2 > 20) idx2 = 20;
            sWp[i] = (1.0f - frac) * pwm[c*21 + idx] + frac * pwm[c*21 + idx2];
        }
    }
    __syncthreads();

    const int wm = wid >> 2, wn = wid & 3;       // 8 x 4 warp grid
    const int m0 = wm * 16, n0 = wn * 32;

    // ldmatrix per-lane geometry (verified passing since R11)
    const int aRow = (mi & 1) * 8 + l8;
    const int aCol = (mi >> 1) * 8;
    const int bRow = ((mi >> 1) & 1) * 8 + l8;
    const int bCol = (mi & 1) * 8;

    for (int s = 0; s < SETS; s++) {
        const int bset = blockIdx.x * SETS + s;

        // ---------- stage X (hi/lo bf16, with constant-1 bias column) ----------
        if (tid < 128) {
            float4 xv = ((const float4*)(x + (size_t)bset * 512))[tid];
            uint32_t* xh = (uint32_t*)(smem + O_XS) + tid*12;
            uint32_t* xl = (uint32_t*)(smem + O_XS + PLANE_X) + tid*12;
            __nv_bfloat16 h0 = __float2bfloat16_rn(xv.x), h1 = __float2bfloat16_rn(xv.y);
            __nv_bfloat16 h2 = __float2bfloat16_rn(xv.z), h3 = __float2bfloat16_rn(xv.w);
            __nv_bfloat162 p01; p01.x = h0; p01.y = h1;
            __nv_bfloat162 p23; p23.x = h2; p23.y = h3;
            __nv_bfloat162 pb;  pb.x  = __float2bfloat16_rn(1.0f); pb.y = __float2bfloat16_rn(0.0f);
            xh[0] = *(uint32_t*)&p01;
            xh[1] = *(uint32_t*)&p23;
            xh[2] = *(uint32_t*)&pb;
            xl[0] = pack_bf16x2(xv.x - __bfloat162float(h0), xv.y - __bfloat162float(h1));
            xl[1] = pack_bf16x2(xv.z - __bfloat162float(h2), xv.w - __bfloat162float(h3));
            xl[2] = 0u;
        }
        __syncthreads();   // X staged; prev set's Zpart/sPl reads done (A1 region free)

        // ---------- layer 1 via mma: H1 tile [16m x 32j] per warp ----------
        {
            uint32_t w1h[4][2], w1l[4][2];
            #pragma unroll
            for (int np = 0; np < 2; np++) {
                uint32_t addrh = sb + O_W1B + (uint32_t)((n0 + np*16 + bRow)*24 + bCol)*2;
                uint32_t r0,r1,r2,r3;
                LDSM4(r0,r1,r2,r3, addrh);
                w1h[2*np][0]=r0; w1h[2*np][1]=r1; w1h[2*np+1][0]=r2; w1h[2*np+1][1]=r3;
                LDSM4(r0,r1,r2,r3, addrh + PLANE_X);
                w1l[2*np][0]=r0; w1l[2*np][1]=r1; w1l[2*np+1][0]=r2; w1l[2*np+1][1]=r3;
            }
            uint32_t xfh[4], xfl[4];
            {
                uint32_t ah = sb + O_XS + (uint32_t)((m0 + aRow)*24 + aCol)*2;
                LDSM4(xfh[0], xfh[1], xfh[2], xfh[3], ah);
                LDSM4(xfl[0], xfl[1], xfl[2], xfl[3], ah + PLANE_X);
            }
            float c1[4][4];
            #pragma unroll
            for (int j = 0; j < 4; j++)
                #pragma unroll
                for (int r = 0; r < 4; r++) c1[j][r] = 0.0f;
            #pragma unroll
            for (int nf = 0; nf < 4; nf++) {
                MMA(c1[nf], xfh, w1h[nf]);
                MMA(c1[nf], xfh, w1l[nf]);
                MMA(c1[nf], xfl, w1h[nf]);
            }
            uint32_t* a1h = (uint32_t*)(smem + O_A1);
            uint32_t* a1l = (uint32_t*)(smem + O_A1 + PLANE_A);
            #pragma unroll
            for (int nf = 0; nf < 4; nf++)
                #pragma unroll
                for (int h = 0; h < 2; h++) {
                    float v0 = fmaxf(c1[nf][2*h],   0.0f);
                    float v1 = fmaxf(c1[nf][2*h+1], 0.0f);
                    __nv_bfloat16 bh0 = __float2bfloat16_rn(v0);
                    __nv_bfloat16 bh1 = __float2bfloat16_rn(v1);
                    __nv_bfloat162 ph; ph.x = bh0; ph.y = bh1;
                    int m = m0 + g + 8*h;
                    int w = m*(SA/2) + (n0 >> 1) + 4*nf + t4;
                    a1h[w] = *(uint32_t*)&ph;
                    a1l[w] = pack_bf16x2(v0 - __bfloat162float(bh0),
                                         v1 - __bfloat162float(bh1));
                }
        }
        __syncthreads();

        // ---------- layer 2: C[16x32] per warp via mma.sync, 8 k-steps ----------
        float cacc[4][4];
        #pragma unroll
        for (int j = 0; j < 4; j++)
            #pragma unroll
            for (int r = 0; r < 4; r++) cacc[j][r] = 0.0f;
        {
            uint32_t aAddr[2], bAddr[2][2];
            #pragma unroll
            for (int pl = 0; pl < 2; pl++) {
                aAddr[pl] = sb + O_A1 + pl*PLANE_A + (uint32_t)((m0 + aRow)*SA + aCol)*2;
                #pragma unroll
                for (int np = 0; np < 2; np++)
                    bAddr[pl][np] = sb + O_W2B + pl*PLANE_W2
                                  + (uint32_t)((n0 + np*16 + bRow)*SA + bCol)*2;
            }
            #pragma unroll
            for (int kk = 0; kk < 8; kk++) {
                uint32_t af[2][4];
                #pragma unroll
                for (int pl = 0; pl < 2; pl++)
                    LDSM4(af[pl][0], af[pl][1], af[pl][2], af[pl][3], aAddr[pl] + kk*32);
                uint32_t bfr[2][4][2];
                #pragma unroll
                for (int pl = 0; pl < 2; pl++)
                    #pragma unroll
                    for (int np = 0; np < 2; np++) {
                        uint32_t r0,r1,r2,r3;
                        LDSM4(r0,r1,r2,r3, bAddr[pl][np] + kk*32);
                        bfr[pl][2*np][0]=r0; bfr[pl][2*np][1]=r1;
                        bfr[pl][2*np+1][0]=r2; bfr[pl][2*np+1][1]=r3;
                    }
                #pragma unroll
                for (int nf = 0; nf < 4; nf++) {
                    MMA(cacc[nf], af[0], bfr[0][nf]);   // hi*hi
                    MMA(cacc[nf], af[0], bfr[1][nf]);   // hi*lo
                    MMA(cacc[nf], af[1], bfr[0][nf]);   // lo*hi
                }
            }
        }

        // ---------- epilogue in registers: bias + relu + hi/lo split ----------
        uint32_t Ah[2][4], Al[2][4];               // [kf][reg]
        {
            const float* sb2 = (const float*)(smem + O_B2);
            #pragma unroll
            for (int nf = 0; nf < 4; nf++) {
                float bv0 = sb2[n0 + 8*nf + 2*t4];
                float bv1 = sb2[n0 + 8*nf + 2*t4 + 1];
                cacc[nf][0] = fmaxf(cacc[nf][0] + bv0, 0.0f);
                cacc[nf][1] = fmaxf(cacc[nf][1] + bv1, 0.0f);
                cacc[nf][2] = fmaxf(cacc[nf][2] + bv0, 0.0f);
                cacc[nf][3] = fmaxf(cacc[nf][3] + bv1, 0.0f);
            }
            #pragma unroll
            for (int kf = 0; kf < 2; kf++) {
                const float* cL = cacc[2*kf];
                const float* cH = cacc[2*kf+1];
                #pragma unroll
                for (int h = 0; h < 2; h++) {
                    float v0 = cL[2*h], v1 = cL[2*h+1];
                    float w0 = cH[2*h], w1 = cH[2*h+1];
                    __nv_bfloat16 b0 = __float2bfloat16_rn(v0);
                    __nv_bfloat16 b1_ = __float2bfloat16_rn(v1);
                    __nv_bfloat16 b2_ = __float2bfloat16_rn(w0);
                    __nv_bfloat16 b3_ = __float2bfloat16_rn(w1);
                    __nv_bfloat162 p0; p0.x = b0;  p0.y = b1_;
                    __nv_bfloat162 p1; p1.x = b2_; p1.y = b3_;
                    Ah[kf][h]   = *(uint32_t*)&p0;
                    Ah[kf][2+h] = *(uint32_t*)&p1;
                    Al[kf][h]   = pack_bf16x2(v0 - __bfloat162float(b0),
                                              v1 - __bfloat162float(b1_));
                    Al[kf][2+h] = pack_bf16x2(w0 - __bfloat162float(b2_),
                                              w1 - __bfloat162float(b3_));
                }
            }
        }

        // ---------- layer 3: partial Z[16m x 32ch] over this warp's k-slice ----------
        float zacc[4][4];
        #pragma unroll
        for (int j = 0; j < 4; j++)
            #pragma unroll
            for (int r = 0; r < 4; r++) zacc[j][r] = 0.0f;
        #pragma unroll
        for (int cp = 0; cp < 2; cp++) {           // chf pairs {0,1},{2,3}
            #pragma unroll
            for (int kf = 0; kf < 2; kf++) {
                uint32_t addrh = sb + O_W3B + (uint32_t)((cp*16 + bRow)*SA + n0 + kf*16 + bCol)*2;
                uint32_t r0,r1,r2,r3;
                LDSM4(r0,r1,r2,r3, addrh);
                uint32_t q0,q1,q2,q3;
                LDSM4(q0,q1,q2,q3, addrh + PLANE_W3);
                uint32_t bh0[2] = {r0, r1}, bl0[2] = {q0, q1};
                uint32_t bh1[2] = {r2, r3}, bl1[2] = {q2, q3};
                MMA(zacc[2*cp],   Ah[kf], bh0);
                MMA(zacc[2*cp],   Ah[kf], bl0);
                MMA(zacc[2*cp],   Al[kf], bh0);
                MMA(zacc[2*cp+1], Ah[kf], bh1);
                MMA(zacc[2*cp+1], Ah[kf], bl1);
                MMA(zacc[2*cp+1], Al[kf], bh1);
            }
        }

        __syncthreads();   // ldmatrix reads of A1/W2 done -> Zpart may alias A1

        // ---------- store partial Z: Zpart[wn][ch][132] ----------
        {
            float* zp = (float*)(smem + O_ZP) + wn * 4224;
            #pragma unroll
            for (int chf = 0; chf < 4; chf++) {
                int ch = 8*chf + 2*t4;
                int m  = m0 + g;
                zp[ch*132 + m]         = zacc[chf][0];
                zp[(ch+1)*132 + m]     = zacc[chf][1];
                zp[ch*132 + m + 8]     = zacc[chf][2];
                zp[(ch+1)*132 + m + 8] = zacc[chf][3];
            }
        }
        __syncthreads();

        // ---------- lane-major bitonic sorted-dot pool (1 channel per warp) ----------
        {
            const float* sb3 = (const float*)(smem + O_B3);
            const float* zp0 = (const float*)(smem + O_ZP);
            float* sPl = (float*)(smem + O_PL);
            const int c = wid;
            const float bias = sb3[c];
            // idx = 4*lane + r  (lane-major): contiguous float4 loads
            float v[4];
            {
                const float4 za = *(const float4*)(zp0 + c*132 + 4*lane);
                const float4 zb = *(const float4*)(zp0 + 4224  + c*132 + 4*lane);
                const float4 zc = *(const float4*)(zp0 + 8448  + c*132 + 4*lane);
                const float4 zd = *(const float4*)(zp0 + 12672 + c*132 + 4*lane);
                v[0] = za.x + zb.x + zc.x + zd.x + bias;
                v[1] = za.y + zb.y + zc.y + zd.y + bias;
                v[2] = za.z + zb.z + zc.z + zd.z + bias;
                v[3] = za.w + zb.w + zc.w + zd.w + bias;
            }
            #pragma unroll
            for (int k = 2; k <= 128; k <<= 1) {
                #pragma unroll
                for (int st = 64; st >= 1; st >>= 1) {
                    if (st >= k) continue;
                    if (st >= 4) {
                        const int ld = st >> 2;
                        const bool lowerLane = ((lane & ld) == 0);
                        #pragma unroll
                        for (int r = 0; r < 4; r++) {
                            float o = __shfl_xor_sync(0xffffffffu, v[r], ld);
                            bool up = (((4*lane + r) & k) == 0);
                            bool tmin = (up == lowerLane);
                            float mn = fminf(v[r], o), mx = fmaxf(v[r], o);
                            v[r] = tmin ? mn : mx;
                        }
                    } else if (st == 2) {
                        #pragma unroll
                        for (int ra = 0; ra < 2; ra++) {
                            bool up = (((4*lane + ra) & k) == 0);
                            float mn = fminf(v[ra], v[ra+2]), mx = fmaxf(v[ra], v[ra+2]);
                            v[ra]   = up ? mn : mx;
                            v[ra+2] = up ? mx : mn;
                        }
                    } else {    // st == 1
                        #pragma unroll
                        for (int ra = 0; ra < 4; ra += 2) {
                            bool up = (((4*lane + ra) & k) == 0);
                            float mn = fminf(v[ra], v[ra+1]), mx = fmaxf(v[ra], v[ra+1]);
                            v[ra]   = up ? mn : mx;
                            v[ra+1] = up ? mx : mn;
                        }
                    }
                }
            }
            // ascending idx = 4*lane + r  ->  descending rank = 127 - idx
            const float* wc = sWp + c * 128;
            const float4 w4 = *(const float4*)(wc + 124 - 4*lane);   // w4[q] = wc[124-4*lane+q]
            float sum = v[0] * w4.w + v[1] * w4.z + v[2] * w4.y + v[3] * w4.x;
            #pragma unroll
            for (int ofs = 16; ofs > 0; ofs >>= 1)
                sum += __shfl_xor_sync(0xffffffffu, sum, ofs);
            if (lane == 0) sPl[c] = sum;
        }
        __syncthreads();

        // ---------- reparameterize + write ----------
        if (tid < NLAT) {
            const float* sPl = (const float*)(smem + O_PL);
            float mu = sPl[2*tid];
            float lv = sPl[2*tid + 1];
            float e  = eps[(size_t)bset*NLAT + tid];
            float smp = fmaf(e, expf(0.5f * lv), mu);
            out[(size_t)bset*NLAT + tid] = mu;
            out[(size_t)(NBATCH*NLAT)   + (size_t)bset*NLAT + tid] = lv;
            out[(size_t)(2*NBATCH*NLAT) + (size_t)bset*NLAT + tid] = smp;
        }
        __syncthreads();   // sPl/Zpart reads done before next set overwrites
    }
}

extern "C" void kernel_launch(void* const* d_in, const int* in_sizes, int n_in,
                              void* d_out, int out_size) {
    const float* x   = (const float*)d_in[0];
    const float* W1  = (const float*)d_in[1];
    const float* b1  = (const float*)d_in[2];
    const float* W2  = (const float*)d_in[3];
    const float* b2  = (const float*)d_in[4];
    const float* W3  = (const float*)d_in[5];
    const float* b3  = (const float*)d_in[6];
    const float* pwm = (const float*)d_in[7];
    const float* eps = (const float*)d_in[8];
    float* out = (float*)d_out;

    cudaFuncSetAttribute(enc_kernel, cudaFuncAttributeMaxDynamicSharedMemorySize, SMEM_BYTES);
    enc_kernel<<<GRID, TPB, SMEM_BYTES>>>(x, W1, b1, W2, b2, W3, b3, pwm, eps, out);
}

// round 16
// speedup vs baseline: 1.6593x; 1.0266x over previous
#include <cuda_runtime.h>
#include <cuda_bf16.h>
#include <cstdint>

#define NBATCH 8192
#define SETS   8
#define GRID   (NBATCH/SETS)
#define TPB    1024
#define NLAT   16

#define SA 136            // halfword stride for A1/W2/W3 [.][k] bf16 arrays
#define PLANE_A  34816    // 128*136*2 bytes
#define PLANE_W2 34816
#define PLANE_W3 8704     // 32*136*2
#define PLANE_X  6144     // 128*24*2

// ---------------- shared memory layout (bytes) ----------------
#define O_W2B 0           // W2 as B: [n=128][k=136] bf16, hi+lo planes (69632)
#define O_W3B 69632       // W3 as B: [n=32][k=136] bf16, hi+lo planes (17408)
#define O_A1  87040       // A: [m=128][k=136] bf16, hi+lo planes (69632)
#define O_ZP  87040       // alias: Zpart[4][32][132] f32 = 67584
#define O_WP  156672      // fspool weights f32 [32][128] (16384)
#define O_W1B 173056      // [W1T|b1] bf16 [128][24] hi+lo planes (12288)
#define O_B2  185344      // 512
#define O_B3  185856      // 128
#define O_PL  185984      // 128
#define SMEM_BYTES 186112

__device__ __forceinline__ uint32_t cvta_smem(const void* p) {
    uint32_t a;
    asm("{ .reg .u64 t; cvta.to.shared.u64 t, %1; cvt.u32.u64 %0, t; }" : "=r"(a) : "l"(p));
    return a;
}
__device__ __forceinline__ uint32_t pack_bf16x2(float lo, float hi) {
    __nv_bfloat162 t;
    t.x = __float2bfloat16_rn(lo);
    t.y = __float2bfloat16_rn(hi);
    return *(uint32_t*)&t;
}

#define LDSM4(R0,R1,R2,R3,ADDR) \
    asm volatile("ldmatrix.sync.aligned.m8n8.x4.shared.b16 {%0,%1,%2,%3}, [%4];" \
        : "=r"(R0),"=r"(R1),"=r"(R2),"=r"(R3) : "r"(ADDR) : "memory")

#define MMA(C,A,B) \
    asm volatile("mma.sync.aligned.m16n8k16.row.col.f32.bf16.bf16.f32 " \
        "{%0,%1,%2,%3}, {%4,%5,%6,%7}, {%8,%9}, {%0,%1,%2,%3};" \
        : "+f"((C)[0]),"+f"((C)[1]),"+f"((C)[2]),"+f"((C)[3]) \
        : "r"((A)[0]),"r"((A)[1]),"r"((A)[2]),"r"((A)[3]), "r"((B)[0]),"r"((B)[1]))

__global__ __launch_bounds__(TPB, 1)
void enc_kernel(const float* __restrict__ x,  const float* __restrict__ W1,
                const float* __restrict__ b1, const float* __restrict__ W2,
                const float* __restrict__ b2, const float* __restrict__ W3,
                const float* __restrict__ b3, const float* __restrict__ pwm,
                const float* __restrict__ eps, float* __restrict__ out)
{
    extern __shared__ __align__(1024) char smem[];
    const uint32_t sb = cvta_smem(smem);
    const int tid = threadIdx.x;
    const int wid = tid >> 5, lane = tid & 31;
    const int g = lane >> 2, t4 = lane & 3;
    const int l8 = lane & 7, mi = lane >> 3;

    __nv_bfloat16* sW2B = (__nv_bfloat16*)(smem + O_W2B);
    __nv_bfloat16* sW3B = (__nv_bfloat16*)(smem + O_W3B);
    float* sWp = (float*)(smem + O_WP);

    // ---------- stage invariant weights ----------
    {
        #pragma unroll 4
        for (int r = 0; r < 16; r++) {
            int i = tid + r * TPB;               // i = j*128 + n
            float v = W2[i];
            __nv_bfloat16 hi = __float2bfloat16_rn(v);
            __nv_bfloat16 lo = __float2bfloat16_rn(v - __bfloat162float(hi));
            int j = i >> 7, n = i & 127;
            sW2B[n*SA + j] = hi;
            sW2B[PLANE_W2/2 + n*SA + j] = lo;
        }
        #pragma unroll
        for (int r = 0; r < 4; r++) {
            int i = tid + r * TPB;               // i = k*32 + c
            float v = W3[i];
            __nv_bfloat16 hi = __float2bfloat16_rn(v);
            __nv_bfloat16 lo = __float2bfloat16_rn(v - __bfloat162float(hi));
            int k = i >> 5, c = i & 31;
            sW3B[c*SA + k] = hi;
            sW3B[PLANE_W3/2 + c*SA + k] = lo;
        }
        // W1B: row j, cols 0..3 = W1[f][j], col 4 = b1[j], rest 0.
        if (tid < 128) {
            int j = tid;
            uint32_t* wh = (uint32_t*)(smem + O_W1B) + j*12;
            uint32_t* wl = (uint32_t*)(smem + O_W1B + PLANE_X) + j*12;
            #pragma unroll
            for (int q = 0; q < 12; q++) { wh[q] = 0u; wl[q] = 0u; }
            float w0 = W1[j], w1 = W1[128 + j], w2_ = W1[256 + j], w3_ = W1[384 + j];
            float bb = b1[j];
            __nv_bfloat16 h0 = __float2bfloat16_rn(w0), h1 = __float2bfloat16_rn(w1);
            __nv_bfloat16 h2 = __float2bfloat16_rn(w2_), h3 = __float2bfloat16_rn(w3_);
            __nv_bfloat16 hb = __float2bfloat16_rn(bb);
            __nv_bfloat162 p01; p01.x = h0; p01.y = h1;
            __nv_bfloat162 p23; p23.x = h2; p23.y = h3;
            __nv_bfloat162 pb;  pb.x  = hb; pb.y  = __float2bfloat16_rn(0.0f);
            wh[0] = *(uint32_t*)&p01;
            wh[1] = *(uint32_t*)&p23;
            wh[2] = *(uint32_t*)&pb;
            wl[0] = pack_bf16x2(w0 - __bfloat162float(h0), w1 - __bfloat162float(h1));
            wl[1] = pack_bf16x2(w2_ - __bfloat162float(h2), w3_ - __bfloat162float(h3));
            wl[2] = pack_bf16x2(bb - __bfloat162float(hb), 0.0f);
        }
        if (tid >= 160 && tid < 192) ((float4*)(smem + O_B2))[tid-160] = ((const float4*)b2)[tid-160];
        if (tid >= 192 && tid < 200) ((float4*)(smem + O_B3))[tid-192] = ((const float4*)b3)[tid-192];
        #pragma unroll
        for (int r = 0; r < 4; r++) {
            int i = tid + r * TPB;
            int c = i >> 7, pp = i & 127;
            float pos = (float)pp / 127.0f * 20.0f;
            int idx = (int)pos; if (idx > 20) idx = 20;
            float frac = pos - (float)idx;
            int idx2 = idx + 1; if (idx2 > 20) idx2 = 20;
            sWp[i] = (1.0f - frac) * pwm[c*21 + idx] + frac * pwm[c*21 + idx2];
        }
    }
    __syncthreads();

    const int wm = wid >> 2, wn = wid & 3;       // 8 x 4 warp grid
    const int m0 = wm * 16, n0 = wn * 32;

    // ldmatrix per-lane geometry (verified passing since R11)
    const int aRow = (mi & 1) * 8 + l8;
    const int aCol = (mi >> 1) * 8;
    const int bRow = ((mi >> 1) & 1) * 8 + l8;
    const int bCol = (mi & 1) * 8;

    for (int s = 0; s < SETS; s++) {
        const int bset = blockIdx.x * SETS + s;

        // ---------- layer 1 via mma: X fragments built directly from global ----------
        {
            uint32_t xfh[4], xfl[4];
            xfh[2] = 0u; xfh[3] = 0u; xfl[2] = 0u; xfl[3] = 0u;
            if (t4 < 2) {
                const float2* xg = (const float2*)(x + (size_t)bset * 512);
                float2 v0 = xg[(m0 + g) * 2 + t4];        // row m0+g, cols {2t4, 2t4+1}
                float2 v1 = xg[(m0 + g + 8) * 2 + t4];    // row m0+g+8
                __nv_bfloat16 h00 = __float2bfloat16_rn(v0.x), h01 = __float2bfloat16_rn(v0.y);
                __nv_bfloat16 h10 = __float2bfloat16_rn(v1.x), h11 = __float2bfloat16_rn(v1.y);
                __nv_bfloat162 p0; p0.x = h00; p0.y = h01;
                __nv_bfloat162 p1; p1.x = h10; p1.y = h11;
                xfh[0] = *(uint32_t*)&p0;
                xfh[1] = *(uint32_t*)&p1;
                xfl[0] = pack_bf16x2(v0.x - __bfloat162float(h00), v0.y - __bfloat162float(h01));
                xfl[1] = pack_bf16x2(v1.x - __bfloat162float(h10), v1.y - __bfloat162float(h11));
            } else if (t4 == 2) {
                __nv_bfloat162 pone;
                pone.x = __float2bfloat16_rn(1.0f);
                pone.y = __float2bfloat16_rn(0.0f);
                xfh[0] = *(uint32_t*)&pone;   // col 4 = bias column of ones
                xfh[1] = xfh[0];
                xfl[0] = 0u; xfl[1] = 0u;
            } else {
                xfh[0] = 0u; xfh[1] = 0u; xfl[0] = 0u; xfl[1] = 0u;
            }

            uint32_t w1h[4][2], w1l[4][2];
            #pragma unroll
            for (int np = 0; np < 2; np++) {
                uint32_t addrh = sb + O_W1B + (uint32_t)((n0 + np*16 + bRow)*24 + bCol)*2;
                uint32_t r0,r1,r2,r3;
                LDSM4(r0,r1,r2,r3, addrh);
                w1h[2*np][0]=r0; w1h[2*np][1]=r1; w1h[2*np+1][0]=r2; w1h[2*np+1][1]=r3;
                LDSM4(r0,r1,r2,r3, addrh + PLANE_X);
                w1l[2*np][0]=r0; w1l[2*np][1]=r1; w1l[2*np+1][0]=r2; w1l[2*np+1][1]=r3;
            }
            float c1[4][4];
            #pragma unroll
            for (int j = 0; j < 4; j++)
                #pragma unroll
                for (int r = 0; r < 4; r++) c1[j][r] = 0.0f;
            #pragma unroll
            for (int nf = 0; nf < 4; nf++) {
                MMA(c1[nf], xfh, w1h[nf]);
                MMA(c1[nf], xfh, w1l[nf]);
                MMA(c1[nf], xfl, w1h[nf]);
            }
            uint32_t* a1h = (uint32_t*)(smem + O_A1);
            uint32_t* a1l = (uint32_t*)(smem + O_A1 + PLANE_A);
            #pragma unroll
            for (int nf = 0; nf < 4; nf++)
                #pragma unroll
                for (int h = 0; h < 2; h++) {
                    float v0 = fmaxf(c1[nf][2*h],   0.0f);
                    float v1 = fmaxf(c1[nf][2*h+1], 0.0f);
                    __nv_bfloat16 bh0 = __float2bfloat16_rn(v0);
                    __nv_bfloat16 bh1 = __float2bfloat16_rn(v1);
                    __nv_bfloat162 ph; ph.x = bh0; ph.y = bh1;
                    int m = m0 + g + 8*h;
                    int w = m*(SA/2) + (n0 >> 1) + 4*nf + t4;
                    a1h[w] = *(uint32_t*)&ph;
                    a1l[w] = pack_bf16x2(v0 - __bfloat162float(bh0),
                                         v1 - __bfloat162float(bh1));
                }
        }
        __syncthreads();   // A1 visible (also orders vs prev set's ZP reads — see pool barrier)

        // ---------- layer 2: C[16x32] per warp via mma.sync, 8 k-steps ----------
        float cacc[4][4];
        #pragma unroll
        for (int j = 0; j < 4; j++)
            #pragma unroll
            for (int r = 0; r < 4; r++) cacc[j][r] = 0.0f;
        {
            uint32_t aAddr[2], bAddr[2][2];
            #pragma unroll
            for (int pl = 0; pl < 2; pl++) {
                aAddr[pl] = sb + O_A1 + pl*PLANE_A + (uint32_t)((m0 + aRow)*SA + aCol)*2;
                #pragma unroll
                for (int np = 0; np < 2; np++)
                    bAddr[pl][np] = sb + O_W2B + pl*PLANE_W2
                                  + (uint32_t)((n0 + np*16 + bRow)*SA + bCol)*2;
            }
            #pragma unroll
            for (int kk = 0; kk < 8; kk++) {
                uint32_t af[2][4];
                #pragma unroll
                for (int pl = 0; pl < 2; pl++)
                    LDSM4(af[pl][0], af[pl][1], af[pl][2], af[pl][3], aAddr[pl] + kk*32);
                uint32_t bfr[2][4][2];
                #pragma unroll
                for (int pl = 0; pl < 2; pl++)
                    #pragma unroll
                    for (int np = 0; np < 2; np++) {
                        uint32_t r0,r1,r2,r3;
                        LDSM4(r0,r1,r2,r3, bAddr[pl][np] + kk*32);
                        bfr[pl][2*np][0]=r0; bfr[pl][2*np][1]=r1;
                        bfr[pl][2*np+1][0]=r2; bfr[pl][2*np+1][1]=r3;
                    }
                #pragma unroll
                for (int nf = 0; nf < 4; nf++) {
                    MMA(cacc[nf], af[0], bfr[0][nf]);   // hi*hi
                    MMA(cacc[nf], af[0], bfr[1][nf]);   // hi*lo
                    MMA(cacc[nf], af[1], bfr[0][nf]);   // lo*hi
                }
            }
        }

        // ---------- epilogue in registers: bias + relu + hi/lo split ----------
        uint32_t Ah[2][4], Al[2][4];               // [kf][reg]
        {
            const float* sb2 = (const float*)(smem + O_B2);
            #pragma unroll
            for (int nf = 0; nf < 4; nf++) {
                float bv0 = sb2[n0 + 8*nf + 2*t4];
                float bv1 = sb2[n0 + 8*nf + 2*t4 + 1];
                cacc[nf][0] = fmaxf(cacc[nf][0] + bv0, 0.0f);
                cacc[nf][1] = fmaxf(cacc[nf][1] + bv1, 0.0f);
                cacc[nf][2] = fmaxf(cacc[nf][2] + bv0, 0.0f);
                cacc[nf][3] = fmaxf(cacc[nf][3] + bv1, 0.0f);
            }
            #pragma unroll
            for (int kf = 0; kf < 2; kf++) {
                const float* cL = cacc[2*kf];
                const float* cH = cacc[2*kf+1];
                #pragma unroll
                for (int h = 0; h < 2; h++) {
                    float v0 = cL[2*h], v1 = cL[2*h+1];
                    float w0 = cH[2*h], w1 = cH[2*h+1];
                    __nv_bfloat16 b0 = __float2bfloat16_rn(v0);
                    __nv_bfloat16 b1_ = __float2bfloat16_rn(v1);
                    __nv_bfloat16 b2_ = __float2bfloat16_rn(w0);
                    __nv_bfloat16 b3_ = __float2bfloat16_rn(w1);
                    __nv_bfloat162 p0; p0.x = b0;  p0.y = b1_;
                    __nv_bfloat162 p1; p1.x = b2_; p1.y = b3_;
                    Ah[kf][h]   = *(uint32_t*)&p0;
                    Ah[kf][2+h] = *(uint32_t*)&p1;
                    Al[kf][h]   = pack_bf16x2(v0 - __bfloat162float(b0),
                                              v1 - __bfloat162float(b1_));
                    Al[kf][2+h] = pack_bf16x2(w0 - __bfloat162float(b2_),
                                              w1 - __bfloat162float(b3_));
                }
            }
        }

        // ---------- layer 3: partial Z[16m x 32ch] over this warp's k-slice ----------
        float zacc[4][4];
        #pragma unroll
        for (int j = 0; j < 4; j++)
            #pragma unroll
            for (int r = 0; r < 4; r++) zacc[j][r] = 0.0f;
        #pragma unroll
        for (int cp = 0; cp < 2; cp++) {           // chf pairs {0,1},{2,3}
            #pragma unroll
            for (int kf = 0; kf < 2; kf++) {
                uint32_t addrh = sb + O_W3B + (uint32_t)((cp*16 + bRow)*SA + n0 + kf*16 + bCol)*2;
                uint32_t r0,r1,r2,r3;
                LDSM4(r0,r1,r2,r3, addrh);
                uint32_t q0,q1,q2,q3;
                LDSM4(q0,q1,q2,q3, addrh + PLANE_W3);
                uint32_t bh0[2] = {r0, r1}, bl0[2] = {q0, q1};
                uint32_t bh1[2] = {r2, r3}, bl1[2] = {q2, q3};
                MMA(zacc[2*cp],   Ah[kf], bh0);
                MMA(zacc[2*cp],   Ah[kf], bl0);
                MMA(zacc[2*cp],   Al[kf], bh0);
                MMA(zacc[2*cp+1], Ah[kf], bh1);
                MMA(zacc[2*cp+1], Ah[kf], bl1);
                MMA(zacc[2*cp+1], Al[kf], bh1);
            }
        }

        __syncthreads();   // ldmatrix reads of A1/W2 done -> Zpart may alias A1

        // ---------- store partial Z: Zpart[wn][ch][132] ----------
        {
            float* zp = (float*)(smem + O_ZP) + wn * 4224;
            #pragma unroll
            for (int chf = 0; chf < 4; chf++) {
                int ch = 8*chf + 2*t4;
                int m  = m0 + g;
                zp[ch*132 + m]         = zacc[chf][0];
                zp[(ch+1)*132 + m]     = zacc[chf][1];
                zp[ch*132 + m + 8]     = zacc[chf][2];
                zp[(ch+1)*132 + m + 8] = zacc[chf][3];
            }
        }
        __syncthreads();

        // ---------- lane-major bitonic sorted-dot pool (1 channel per warp) ----------
        {
            const float* sb3 = (const float*)(smem + O_B3);
            const float* zp0 = (const float*)(smem + O_ZP);
            float* sPl = (float*)(smem + O_PL);
            const int c = wid;
            const float bias = sb3[c];
            // idx = 4*lane + r  (lane-major): contiguous float4 loads
            float v[4];
            {
                const float4 za = *(const float4*)(zp0 + c*132 + 4*lane);
                const float4 zb = *(const float4*)(zp0 + 4224  + c*132 + 4*lane);
                const float4 zc = *(const float4*)(zp0 + 8448  + c*132 + 4*lane);
                const float4 zd = *(const float4*)(zp0 + 12672 + c*132 + 4*lane);
                v[0] = za.x + zb.x + zc.x + zd.x + bias;
                v[1] = za.y + zb.y + zc.y + zd.y + bias;
                v[2] = za.z + zb.z + zc.z + zd.z + bias;
                v[3] = za.w + zb.w + zc.w + zd.w + bias;
            }
            #pragma unroll
            for (int k = 2; k <= 128; k <<= 1) {
                #pragma unroll
                for (int st = 64; st >= 1; st >>= 1) {
                    if (st >= k) continue;
                    if (st >= 4) {
                        const int ld = st >> 2;
                        const bool lowerLane = ((lane & ld) == 0);
                        #pragma unroll
                        for (int r = 0; r < 4; r++) {
                            float o = __shfl_xor_sync(0xffffffffu, v[r], ld);
                            bool up = (((4*lane + r) & k) == 0);
                            bool tmin = (up == lowerLane);
                            float mn = fminf(v[r], o), mx = fmaxf(v[r], o);
                            v[r] = tmin ? mn : mx;
                        }
                    } else if (st == 2) {
                        #pragma unroll
                        for (int ra = 0; ra < 2; ra++) {
                            bool up = (((4*lane + ra) & k) == 0);
                            float mn = fminf(v[ra], v[ra+2]), mx = fmaxf(v[ra], v[ra+2]);
                            v[ra]   = up ? mn : mx;
                            v[ra+2] = up ? mx : mn;
                        }
                    } else {    // st == 1
                        #pragma unroll
                        for (int ra = 0; ra < 4; ra += 2) {
                            bool up = (((4*lane + ra) & k) == 0);
                            float mn = fminf(v[ra], v[ra+1]), mx = fmaxf(v[ra], v[ra+1]);
                            v[ra]   = up ? mn : mx;
                            v[ra+1] = up ? mx : mn;
                        }
                    }
                }
            }
            // ascending idx = 4*lane + r  ->  descending rank = 127 - idx
            const float* wc = sWp + c * 128;
            const float4 w4 = *(const float4*)(wc + 124 - 4*lane);   // w4[q] = wc[124-4*lane+q]
            float sum = v[0] * w4.w + v[1] * w4.z + v[2] * w4.y + v[3] * w4.x;
            #pragma unroll
            for (int ofs = 16; ofs > 0; ofs >>= 1)
                sum += __shfl_xor_sync(0xffffffffu, sum, ofs);
            if (lane == 0) sPl[c] = sum;
        }
        __syncthreads();

        // ---------- reparameterize + write (no trailing barrier needed:
        //            next conflicting write is behind 3 barriers of next set) ----------
        if (tid < NLAT) {
            const float* sPl = (const float*)(smem + O_PL);
            float mu = sPl[2*tid];
            float lv = sPl[2*tid + 1];
            float e  = eps[(size_t)bset*NLAT + tid];
            float smp = fmaf(e, expf(0.5f * lv), mu);
            out[(size_t)bset*NLAT + tid] = mu;
            out[(size_t)(NBATCH*NLAT)   + (size_t)bset*NLAT + tid] = lv;
            out[(size_t)(2*NBATCH*NLAT) + (size_t)bset*NLAT + tid] = smp;
        }
    }
}

extern "C" void kernel_launch(void* const* d_in, const int* in_sizes, int n_in,
                              void* d_out, int out_size) {
    const float* x   = (const float*)d_in[0];
    const float* W1  = (const float*)d_in[1];
    const float* b1  = (const float*)d_in[2];
    const float* W2  = (const float*)d_in[3];
    const float* b2  = (const float*)d_in[4];
    const float* W3  = (const float*)d_in[5];
    const float* b3  = (const float*)d_in[6];
    const float* pwm = (const float*)d_in[7];
    const float* eps = (const float*)d_in[8];
    float* out = (float*)d_out;

    cudaFuncSetAttribute(enc_kernel, cudaFuncAttributeMaxDynamicSharedMemorySize, SMEM_BYTES);
    enc_kernel<<<GRID, TPB, SMEM_BYTES>>>(x, W1, b1, W2, b2, W3, b3, pwm, eps, out);
}